// round 3
// baseline (speedup 1.0000x reference)
#include <cuda_runtime.h>
#include <cuda_bf16.h>
#include <math.h>

// ---------------------------------------------------------------------------
// DeformGCN: 6x GCNConv (PyG norm, self-loops) + LeakyReLU on odd layers,
// then dense [6144x6144] + tanh, *0.1.
//
// Edge dtype note: reference declares int64, but JAX default (x64 disabled)
// produces int32. We detect at runtime: for int64 little-endian data with
// values < 2048, every odd int32 word is 0. k_detect sets g_is64 accordingly
// and edge loads dispatch on it. Indices additionally masked to [0,NN).
// ---------------------------------------------------------------------------

#define NB 16           // batch
#define NN 2048         // nodes
#define NE 12288        // edges
#define MROWS (NB * NN) // 32768 GEMM rows
#define DD 6144         // dense dim (N*3)

// ---- static device scratch (allocation-free rule) ----
__device__ float g_bufG[(size_t)MROWS * 512]; // GEMM output
__device__ float g_bufH[(size_t)MROWS * 512]; // aggregated hidden state
__device__ int   g_cnt[NN];
__device__ int   g_cursor[NN];
__device__ int   g_offs[NN + 1];
__device__ int   g_csr_src[NE];
__device__ float g_csr_norm[NE];
__device__ float g_inv_deg[NN];
__device__ float g_isd[NN];
__device__ int   g_is64;

// ---------------------------------------------------------------------------
// dtype detection + edge load helper
// ---------------------------------------------------------------------------
__global__ void k_detect(const int* __restrict__ e32)
{
    if (threadIdx.x == 0 && blockIdx.x == 0) {
        int allz = 1;
        for (int i = 1; i < 128; i += 2)
            if (e32[i] != 0) allz = 0;
        g_is64 = allz;
    }
}

__device__ __forceinline__ int load_edge(const void* edges, int idx)
{
    int v;
    if (g_is64) v = (int)((const long long*)edges)[idx];
    else        v = ((const int*)edges)[idx];
    return v & (NN - 1); // defensive mask: wrong guess -> wrong value, not trap
}

// ---------------------------------------------------------------------------
// CSR construction
// ---------------------------------------------------------------------------
__global__ void k_zero()
{
    int i = blockIdx.x * blockDim.x + threadIdx.x;
    if (i < NN) { g_cnt[i] = 0; g_cursor[i] = 0; }
}

__global__ void k_count(const void* __restrict__ edges)
{
    int e = blockIdx.x * blockDim.x + threadIdx.x;
    if (e < NE) {
        int d = load_edge(edges, NE + e); // dst
        atomicAdd(&g_cnt[d], 1);
    }
}

// one block, 1024 threads: Hillis-Steele inclusive scan over 2048 counts
__global__ void k_scan_deg()
{
    __shared__ int s[NN];
    int t = threadIdx.x;
    for (int i = t; i < NN; i += 1024) s[i] = g_cnt[i];
    __syncthreads();
    for (int off = 1; off < NN; off <<= 1) {
        int i0 = t, i1 = t + 1024;
        int v0 = (i0 >= off) ? s[i0 - off] : 0;
        int v1 = (i1 >= off) ? s[i1 - off] : 0;
        __syncthreads();
        s[i0] += v0;
        s[i1] += v1;
        __syncthreads();
    }
    for (int i = t; i < NN; i += 1024) {
        g_offs[i + 1] = s[i];
        float deg = (float)g_cnt[i] + 1.0f; // self-loop
        g_inv_deg[i] = 1.0f / deg;
        g_isd[i] = rsqrtf(deg);
    }
    if (t == 0) g_offs[0] = 0;
}

__global__ void k_fill(const void* __restrict__ edges)
{
    int e = blockIdx.x * blockDim.x + threadIdx.x;
    if (e < NE) {
        int s = load_edge(edges, e);
        int d = load_edge(edges, NE + e);
        int pos = g_offs[d] + atomicAdd(&g_cursor[d], 1);
        if (pos < NE) {
            g_csr_src[pos] = s;
            g_csr_norm[pos] = g_isd[s] * g_isd[d];
        }
    }
}

// ---------------------------------------------------------------------------
// SGEMM: g_bufG[M,Nc] = A[M,K] @ W[K,Nc]  (row-major), 128x128x8 tiles,
// 256 threads, 8x8 register micro-tile. A = Aext if useExt else g_bufH.
// ---------------------------------------------------------------------------
#define BM 128
#define BN 128
#define BK 8
#define TM 8
#define TN 8

__global__ __launch_bounds__(256) void k_sgemm(
    const float* __restrict__ Aext, const float* __restrict__ W,
    int M, int K, int Nc, int useExt)
{
    const float* __restrict__ A = useExt ? Aext : (const float*)g_bufH;
    float* __restrict__ C = g_bufG;

    __shared__ float As[BK][BM];
    __shared__ float Bs[BK][BN];

    int tid = threadIdx.x;
    int m0 = blockIdx.y * BM;
    int n0 = blockIdx.x * BN;
    int ty = tid >> 4;      // 0..15
    int tx = tid & 15;      // 0..15

    float acc[TM][TN];
#pragma unroll
    for (int i = 0; i < TM; i++)
#pragma unroll
        for (int j = 0; j < TN; j++) acc[i][j] = 0.0f;

    int aRow = tid >> 1;          // 0..127
    int aK0  = (tid & 1) * 4;     // 0 or 4
    int bCol = tid & 127;         // 0..127
    int bK0  = tid >> 7;          // 0 or 1

    for (int k0 = 0; k0 < K; k0 += BK) {
#pragma unroll
        for (int j = 0; j < 4; j++) {
            int k = k0 + aK0 + j;
            int m = m0 + aRow;
            As[aK0 + j][aRow] = (m < M && k < K) ? A[(size_t)m * K + k] : 0.0f;
        }
#pragma unroll
        for (int j = 0; j < 4; j++) {
            int kk = bK0 + j * 2;
            int k = k0 + kk;
            int n = n0 + bCol;
            Bs[kk][bCol] = (k < K && n < Nc) ? W[(size_t)k * Nc + n] : 0.0f;
        }
        __syncthreads();

#pragma unroll
        for (int kk = 0; kk < BK; kk++) {
            float a[TM], b[TN];
#pragma unroll
            for (int i = 0; i < TM; i++) a[i] = As[kk][ty * TM + i];
#pragma unroll
            for (int j = 0; j < TN; j++) b[j] = Bs[kk][tx * TN + j];
#pragma unroll
            for (int i = 0; i < TM; i++)
#pragma unroll
                for (int j = 0; j < TN; j++)
                    acc[i][j] += a[i] * b[j];
        }
        __syncthreads();
    }

#pragma unroll
    for (int i = 0; i < TM; i++) {
        int m = m0 + ty * TM + i;
        if (m >= M) continue;
#pragma unroll
        for (int j = 0; j < TN; j++) {
            int n = n0 + tx * TN + j;
            if (n < Nc) C[(size_t)m * Nc + n] = acc[i][j];
        }
    }
}

// ---------------------------------------------------------------------------
// Aggregation: g_bufH[b,n,f] = sum_{e in CSR[n]} g_bufG[b,src_e,f]*norm_e
//                              + g_bufG[b,n,f]*inv_deg[n] + bias[f] [+leaky]
// grid (NN, NB), blockDim 256
// ---------------------------------------------------------------------------
__global__ void k_agg(const float* __restrict__ bias, int F, int leaky)
{
    int n = blockIdx.x;
    int b = blockIdx.y;
    const float* hb = g_bufG + (size_t)b * NN * F;
    float* ob = g_bufH + (size_t)b * NN * F;
    int s0 = g_offs[n], s1 = g_offs[n + 1];
    float idg = g_inv_deg[n];

    for (int f = threadIdx.x; f < F; f += blockDim.x) {
        float acc = hb[(size_t)n * F + f] * idg + bias[f];
        for (int e = s0; e < s1; e++) {
            acc += hb[(size_t)g_csr_src[e] * F + f] * g_csr_norm[e];
        }
        if (leaky && acc < 0.0f) acc *= 0.01f;
        ob[(size_t)n * F + f] = acc;
    }
}

// ---------------------------------------------------------------------------
// Dense head: out[b,j] = tanh(sum_k feat[b,k]*Wd[k,j] + bd[j]) * 0.1
// grid 48, blockDim 128 (one output column each).
// ---------------------------------------------------------------------------
__global__ __launch_bounds__(128) void k_dense(
    const float* __restrict__ Wd, const float* __restrict__ bd,
    float* __restrict__ out)
{
    const float* __restrict__ feat = g_bufH;
    __shared__ float sf[NB][128];
    int j = blockIdx.x * 128 + threadIdx.x;

    float acc[NB];
#pragma unroll
    for (int b = 0; b < NB; b++) acc[b] = 0.0f;

    for (int k0 = 0; k0 < DD; k0 += 128) {
        for (int idx = threadIdx.x; idx < NB * 128; idx += 128) {
            int b = idx >> 7, kk = idx & 127;
            sf[b][kk] = feat[(size_t)b * DD + k0 + kk];
        }
        __syncthreads();
#pragma unroll 8
        for (int kk = 0; kk < 128; kk++) {
            float w = Wd[(size_t)(k0 + kk) * DD + j];
#pragma unroll
            for (int b = 0; b < NB; b++) acc[b] += sf[b][kk] * w;
        }
        __syncthreads();
    }

    float bj = bd[j];
#pragma unroll
    for (int b = 0; b < NB; b++)
        out[(size_t)b * DD + j] = tanhf(acc[b] + bj) * 0.1f;
}

// ---------------------------------------------------------------------------
// launch — kernel launches ONLY (graph-capture safe)
// ---------------------------------------------------------------------------
extern "C" void kernel_launch(void* const* d_in, const int* in_sizes, int n_in,
                              void* d_out, int out_size)
{
    const float* x     = (const float*)d_in[0];
    const void*  edges = d_in[1];
    const float* Ws[6] = {(const float*)d_in[2], (const float*)d_in[4],
                          (const float*)d_in[6], (const float*)d_in[8],
                          (const float*)d_in[10], (const float*)d_in[12]};
    const float* bs[6] = {(const float*)d_in[3], (const float*)d_in[5],
                          (const float*)d_in[7], (const float*)d_in[9],
                          (const float*)d_in[11], (const float*)d_in[13]};
    const float* Wd = (const float*)d_in[14];
    const float* bd = (const float*)d_in[15];
    float* out = (float*)d_out;

    // CSR build
    k_detect<<<1, 32>>>((const int*)edges);
    k_zero<<<(NN + 255) / 256, 256>>>();
    k_count<<<(NE + 255) / 256, 256>>>(edges);
    k_scan_deg<<<1, 1024>>>();
    k_fill<<<(NE + 255) / 256, 256>>>(edges);

    const int dims[7] = {1475, 512, 512, 256, 256, 64, 3};
    for (int i = 0; i < 6; i++) {
        int K = dims[i];
        int F = dims[i + 1];
        dim3 gg((F + BN - 1) / BN, (MROWS + BM - 1) / BM);
        k_sgemm<<<gg, 256>>>(x, Ws[i], MROWS, K, F, i == 0 ? 1 : 0);
        dim3 ga(NN, NB);
        k_agg<<<ga, 256>>>(bs[i], F, i & 1);
    }

    k_dense<<<DD / 128, 128>>>(Wd, bd, out);
}

// round 6
// speedup vs baseline: 3.2234x; 3.2234x over previous
#include <cuda_runtime.h>
#include <cuda_bf16.h>
#include <math.h>
#include <stdint.h>

// ---------------------------------------------------------------------------
// DeformGCN on sm_100 (plain target — NO tcgen05; harness compiles -arch=sm_100).
// Tensor cores via mma.sync.m16n8k16 bf16, fused 3-term split precision:
// D = Ahi*Whi + Ahi*Wlo + Alo*Whi, fp32 accumulate.
// ---------------------------------------------------------------------------

#define NB 16
#define NN 2048
#define NE 12288
#define MROWS (NB * NN)   // 32768
#define DD 6144

// ---- static device scratch ----
__device__ __align__(128) float         g_bufG[(size_t)MROWS * 512];
__device__ __align__(128) float         g_bufH[(size_t)MROWS * 512];
__device__ __align__(128) __nv_bfloat16 g_Ahi[(size_t)MROWS * 1536];
__device__ __align__(128) __nv_bfloat16 g_Alo[(size_t)MROWS * 1536];
__device__ __align__(128) __nv_bfloat16 g_Wth[512 * 1536];  // W^T hi [Fpad,Kpad]
__device__ __align__(128) __nv_bfloat16 g_Wtl[512 * 1536];  // W^T lo
__device__ float g_dacc[8 * NB * DD];
__device__ int   g_cnt[NN];
__device__ int   g_cursor[NN];
__device__ int   g_offs[NN + 1];
__device__ int   g_csr_src[NE];
__device__ float g_csr_norm[NE];
__device__ float g_inv_deg[NN];
__device__ float g_isd[NN];
__device__ int   g_is64;

// ---------------------------------------------------------------------------
// helpers
// ---------------------------------------------------------------------------
__device__ __forceinline__ uint32_t smem_u32(const void* p)
{
    uint32_t a;
    asm("{ .reg .u64 t; cvta.to.shared.u64 t, %1; cvt.u32.u64 %0, t; }"
        : "=r"(a) : "l"(p));
    return a;
}

__device__ __forceinline__ void cp_async16(uint32_t saddr, const void* gaddr)
{
    asm volatile("cp.async.cg.shared.global [%0], [%1], 16;"
                 :: "r"(saddr), "l"(gaddr));
}
__device__ __forceinline__ void cp_commit()
{
    asm volatile("cp.async.commit_group;" ::: "memory");
}
__device__ __forceinline__ void cp_wait0()
{
    asm volatile("cp.async.wait_group 0;" ::: "memory");
}

__device__ __forceinline__ void ldmat_x4(uint32_t* r, uint32_t addr)
{
    asm volatile("ldmatrix.sync.aligned.m8n8.x4.shared.b16 {%0,%1,%2,%3}, [%4];"
                 : "=r"(r[0]), "=r"(r[1]), "=r"(r[2]), "=r"(r[3]) : "r"(addr));
}

__device__ __forceinline__ void mma_bf16(float* c, const uint32_t* a,
                                         const uint32_t* b)
{
    asm volatile(
        "mma.sync.aligned.m16n8k16.row.col.f32.bf16.bf16.f32 "
        "{%0,%1,%2,%3}, {%4,%5,%6,%7}, {%8,%9}, {%0,%1,%2,%3};"
        : "+f"(c[0]), "+f"(c[1]), "+f"(c[2]), "+f"(c[3])
        : "r"(a[0]), "r"(a[1]), "r"(a[2]), "r"(a[3]), "r"(b[0]), "r"(b[1]));
}

// ---------------------------------------------------------------------------
// edge dtype detect + CSR build (proven in R3)
// ---------------------------------------------------------------------------
__global__ void k_detect(const int* __restrict__ e32)
{
    if (threadIdx.x == 0 && blockIdx.x == 0) {
        int allz = 1;
        for (int i = 1; i < 128; i += 2)
            if (e32[i] != 0) allz = 0;
        g_is64 = allz;
    }
}

__device__ __forceinline__ int load_edge(const void* edges, int idx)
{
    int v;
    if (g_is64) v = (int)((const long long*)edges)[idx];
    else        v = ((const int*)edges)[idx];
    return v & (NN - 1);
}

__global__ void k_zero()
{
    int i = blockIdx.x * blockDim.x + threadIdx.x;
    if (i < NN) { g_cnt[i] = 0; g_cursor[i] = 0; }
}

__global__ void k_count(const void* __restrict__ edges)
{
    int e = blockIdx.x * blockDim.x + threadIdx.x;
    if (e < NE) atomicAdd(&g_cnt[load_edge(edges, NE + e)], 1);
}

__global__ void k_scan_deg()
{
    __shared__ int s[NN];
    int t = threadIdx.x;
    for (int i = t; i < NN; i += 1024) s[i] = g_cnt[i];
    __syncthreads();
    for (int off = 1; off < NN; off <<= 1) {
        int i0 = t, i1 = t + 1024;
        int v0 = (i0 >= off) ? s[i0 - off] : 0;
        int v1 = (i1 >= off) ? s[i1 - off] : 0;
        __syncthreads();
        s[i0] += v0;
        s[i1] += v1;
        __syncthreads();
    }
    for (int i = t; i < NN; i += 1024) {
        g_offs[i + 1] = s[i];
        float deg = (float)g_cnt[i] + 1.0f;
        g_inv_deg[i] = 1.0f / deg;
        g_isd[i] = rsqrtf(deg);
    }
    if (t == 0) g_offs[0] = 0;
}

__global__ void k_fill(const void* __restrict__ edges)
{
    int e = blockIdx.x * blockDim.x + threadIdx.x;
    if (e < NE) {
        int s = load_edge(edges, e);
        int d = load_edge(edges, NE + e);
        int pos = g_offs[d] + atomicAdd(&g_cursor[d], 1);
        if (pos < NE) {
            g_csr_src[pos] = s;
            g_csr_norm[pos] = g_isd[s] * g_isd[d];
        }
    }
}

// ---------------------------------------------------------------------------
// conversions: fp32 -> bf16 hi/lo
// ---------------------------------------------------------------------------
__global__ void k_convX(const float* __restrict__ x)
{
    size_t idx = (size_t)blockIdx.x * blockDim.x + threadIdx.x;
    if (idx >= (size_t)MROWS * 1536) return;
    int c = (int)(idx % 1536);
    size_t m = idx / 1536;
    float v = (c < 1475) ? x[m * 1475 + c] : 0.0f;
    __nv_bfloat16 hi = __float2bfloat16(v);
    g_Ahi[idx] = hi;
    g_Alo[idx] = __float2bfloat16(v - __bfloat162float(hi));
}

// W [K,F] -> Wt hi/lo [Fpad,Kpad] (transposed, zero-padded)
__global__ void k_convW(const float* __restrict__ W, int K, int F,
                        int Kpad, int Fpad)
{
    int idx = blockIdx.x * blockDim.x + threadIdx.x;
    if (idx >= Fpad * Kpad) return;
    int n = idx / Kpad;
    int k = idx % Kpad;
    float v = (k < K && n < F) ? W[(size_t)k * F + n] : 0.0f;
    __nv_bfloat16 hi = __float2bfloat16(v);
    g_Wth[idx] = hi;
    g_Wtl[idx] = __float2bfloat16(v - __bfloat162float(hi));
}

// ---------------------------------------------------------------------------
// mma.sync bf16 GEMM, fused 3-term split precision.
// Block 128x128x32, 8 warps (4x2), warp tile 32x64.
// SMEM stage: Ahi|Alo|Bhi|Blo, each 128 rows x 80B (64B data + 16B pad).
// ---------------------------------------------------------------------------
#define ROWB 80
#define REG_A 10240                 // 128*80
#define STAGE (4 * REG_A)           // 40960
#define SMEM_GEMM (2 * STAGE)       // 81920

__global__ __launch_bounds__(256) void k_gemm_mma(int Kpad, int F)
{
    extern __shared__ char smem[];
    uint32_t sb = smem_u32(smem);

    int tid = threadIdx.x;
    int lane = tid & 31;
    int warp = tid >> 5;
    int wm = warp >> 1;          // 0..3
    int wn = warp & 1;           // 0..1
    int m0 = blockIdx.x * 128;
    int n0 = blockIdx.y * 128;

    // ldmatrix lane addressing
    int a_row = (lane & 7) + ((lane >> 3) & 1) * 8;      // + mi*16
    int a_kb  = ((lane >> 4) & 1) * 16;                  // + kk*32
    int b_row = (lane & 7) + ((lane >> 4) & 1) * 8;      // + g*16 (+wn*64)
    int b_kb  = ((lane >> 3) & 1) * 16;                  // + kk*32

    float acc[2][8][4];
#pragma unroll
    for (int i = 0; i < 2; i++)
#pragma unroll
        for (int j = 0; j < 8; j++)
#pragma unroll
            for (int q = 0; q < 4; q++) acc[i][j][q] = 0.0f;

    const int nst = Kpad >> 5;

    auto load_stage = [&](int s, int k0) {
        uint32_t base = sb + (uint32_t)s * STAGE;
#pragma unroll
        for (int t = 0; t < 2; t++) {
            int idx = tid + t * 256;          // 0..511
            int row = idx >> 2;
            int c = idx & 3;
            uint32_t so = (uint32_t)row * ROWB + (uint32_t)c * 16;
            size_t goA = (size_t)(m0 + row) * Kpad + k0 + c * 8;
            size_t goB = (size_t)(n0 + row) * Kpad + k0 + c * 8;
            cp_async16(base + so,               g_Ahi + goA);
            cp_async16(base + REG_A + so,       g_Alo + goA);
            cp_async16(base + 2 * REG_A + so,   g_Wth + goB);
            cp_async16(base + 3 * REG_A + so,   g_Wtl + goB);
        }
        cp_commit();
    };

    load_stage(0, 0);

    for (int st = 0; st < nst; st++) {
        cp_wait0();
        __syncthreads();
        if (st + 1 < nst) load_stage((st + 1) & 1, (st + 1) * 32);

        uint32_t base = sb + (uint32_t)(st & 1) * STAGE;
#pragma unroll
        for (int kk = 0; kk < 2; kk++) {
            uint32_t ahi[2][4], alo[2][4];
#pragma unroll
            for (int mi = 0; mi < 2; mi++) {
                uint32_t ar = (uint32_t)(wm * 32 + mi * 16 + a_row) * ROWB
                              + a_kb + kk * 32;
                ldmat_x4(ahi[mi], base + ar);
                ldmat_x4(alo[mi], base + REG_A + ar);
            }
#pragma unroll
            for (int g = 0; g < 4; g++) {
                uint32_t bhi[4], blo[4];
                uint32_t br = (uint32_t)(wn * 64 + g * 16 + b_row) * ROWB
                              + b_kb + kk * 32;
                ldmat_x4(bhi, base + 2 * REG_A + br);
                ldmat_x4(blo, base + 3 * REG_A + br);
#pragma unroll
                for (int mi = 0; mi < 2; mi++) {
#pragma unroll
                    for (int pr = 0; pr < 2; pr++) {
                        float* c = acc[mi][g * 2 + pr];
                        mma_bf16(c, ahi[mi], bhi + pr * 2);
                        mma_bf16(c, ahi[mi], blo + pr * 2);
                        mma_bf16(c, alo[mi], bhi + pr * 2);
                    }
                }
            }
        }
        __syncthreads();
    }

    // epilogue: direct float2 stores, guard col < F
#pragma unroll
    for (int mi = 0; mi < 2; mi++) {
#pragma unroll
        for (int n8 = 0; n8 < 8; n8++) {
            int col = n0 + wn * 64 + (n8 >> 1) * 16 + (n8 & 1) * 8 + (lane & 3) * 2;
            if (col >= F) continue;
            int row = m0 + wm * 32 + mi * 16 + (lane >> 2);
            float2 v0 = make_float2(acc[mi][n8][0], acc[mi][n8][1]);
            float2 v1 = make_float2(acc[mi][n8][2], acc[mi][n8][3]);
            *(float2*)&g_bufG[(size_t)row * F + col] = v0;
            *(float2*)&g_bufG[(size_t)(row + 8) * F + col] = v1;
        }
    }
}

// ---------------------------------------------------------------------------
// aggregation: gather + self + bias [+leaky]; output fp32 OR bf16 hi/lo
// ---------------------------------------------------------------------------
__global__ __launch_bounds__(128) void k_agg2(const float* __restrict__ bias,
                                              int F, int leaky, int splitOut)
{
    int n = blockIdx.x;
    int b = blockIdx.y;
    const float* hb = g_bufG + (size_t)b * NN * F;
    int s0 = g_offs[n], s1 = g_offs[n + 1];
    float idg = g_inv_deg[n];
    size_t obase = ((size_t)b * NN + n) * F;

    int F4 = F >> 2;
    const float4* hb4 = (const float4*)hb;
    const float4* b4 = (const float4*)bias;
    for (int f = threadIdx.x; f < F4; f += 128) {
        float4 a = hb4[(size_t)n * F4 + f];
        float4 bb = b4[f];
        a.x = a.x * idg + bb.x; a.y = a.y * idg + bb.y;
        a.z = a.z * idg + bb.z; a.w = a.w * idg + bb.w;
        for (int e = s0; e < s1; e++) {
            float nr = g_csr_norm[e];
            float4 v = hb4[(size_t)g_csr_src[e] * F4 + f];
            a.x += v.x * nr; a.y += v.y * nr; a.z += v.z * nr; a.w += v.w * nr;
        }
        if (leaky) {
            if (a.x < 0.f) a.x *= 0.01f;
            if (a.y < 0.f) a.y *= 0.01f;
            if (a.z < 0.f) a.z *= 0.01f;
            if (a.w < 0.f) a.w *= 0.01f;
        }
        size_t o = obase + (size_t)f * 4;
        if (splitOut) {
            float vv[4] = {a.x, a.y, a.z, a.w};
#pragma unroll
            for (int q = 0; q < 4; q++) {
                __nv_bfloat16 hi = __float2bfloat16(vv[q]);
                g_Ahi[o + q] = hi;
                g_Alo[o + q] = __float2bfloat16(vv[q] - __bfloat162float(hi));
            }
        } else {
            *(float4*)&g_bufH[o] = a;
        }
    }
}

// F=3 tail aggregation (scalar path, layer 5 — leaky)
__global__ __launch_bounds__(128) void k_agg3(const float* __restrict__ bias)
{
    int n = blockIdx.x;
    int b = blockIdx.y;
    const int F = 3;
    const float* hb = g_bufG + (size_t)b * NN * F;
    int s0 = g_offs[n], s1 = g_offs[n + 1];
    float idg = g_inv_deg[n];
    size_t obase = ((size_t)b * NN + n) * F;
    for (int f = threadIdx.x; f < F; f += 128) {
        float acc = hb[(size_t)n * F + f] * idg + bias[f];
        for (int e = s0; e < s1; e++)
            acc += hb[(size_t)g_csr_src[e] * F + f] * g_csr_norm[e];
        if (acc < 0.0f) acc *= 0.01f;
        g_bufH[obase + f] = acc;
    }
}

// ---------------------------------------------------------------------------
// layer 5 GEMM (64 -> 3), SIMT
// ---------------------------------------------------------------------------
__global__ __launch_bounds__(256) void k_gemm5(const float* __restrict__ W5)
{
    __shared__ float w[64 * 3];
    if (threadIdx.x < 192) w[threadIdx.x] = W5[threadIdx.x];
    __syncthreads();
    int m = blockIdx.x * blockDim.x + threadIdx.x;
    if (m >= MROWS) return;
    const float* h = g_bufH + (size_t)m * 64;
    float a0 = 0.f, a1 = 0.f, a2 = 0.f;
#pragma unroll
    for (int k = 0; k < 64; k++) {
        float v = h[k];
        a0 += v * w[k * 3 + 0];
        a1 += v * w[k * 3 + 1];
        a2 += v * w[k * 3 + 2];
    }
    g_bufG[(size_t)m * 3 + 0] = a0;
    g_bufG[(size_t)m * 3 + 1] = a1;
    g_bufG[(size_t)m * 3 + 2] = a2;
}

// ---------------------------------------------------------------------------
// dense head: split-K partials + finalize
// ---------------------------------------------------------------------------
__global__ __launch_bounds__(128) void k_dense_part(const float* __restrict__ Wd)
{
    const float* feat = g_bufH;
    __shared__ float sf[NB][128];
    int j = blockIdx.x * 128 + threadIdx.x;
    int kc = blockIdx.y;
    int kbase = kc * 768;

    float acc[NB];
#pragma unroll
    for (int b = 0; b < NB; b++) acc[b] = 0.0f;

    for (int kb = 0; kb < 768; kb += 128) {
        for (int idx = threadIdx.x; idx < NB * 128; idx += 128) {
            int b = idx >> 7, kk = idx & 127;
            sf[b][kk] = feat[(size_t)b * DD + kbase + kb + kk];
        }
        __syncthreads();
#pragma unroll 8
        for (int kk = 0; kk < 128; kk++) {
            float w = Wd[(size_t)(kbase + kb + kk) * DD + j];
#pragma unroll
            for (int b = 0; b < NB; b++) acc[b] += sf[b][kk] * w;
        }
        __syncthreads();
    }
#pragma unroll
    for (int b = 0; b < NB; b++)
        g_dacc[((size_t)kc * NB + b) * DD + j] = acc[b];
}

__global__ __launch_bounds__(256) void k_dense_fin(const float* __restrict__ bd,
                                                   float* __restrict__ out)
{
    int idx = blockIdx.x * blockDim.x + threadIdx.x;
    if (idx >= NB * DD) return;
    int b = idx / DD, j = idx % DD;
    float s = bd[j];
#pragma unroll
    for (int kc = 0; kc < 8; kc++)
        s += g_dacc[((size_t)kc * NB + b) * DD + j];
    out[idx] = tanhf(s) * 0.1f;
}

// ---------------------------------------------------------------------------
// launch — kernel launches only (plus one idempotent attribute set)
// ---------------------------------------------------------------------------
extern "C" void kernel_launch(void* const* d_in, const int* in_sizes, int n_in,
                              void* d_out, int out_size)
{
    const float* x     = (const float*)d_in[0];
    const void*  edges = d_in[1];
    const float* Ws[6] = {(const float*)d_in[2], (const float*)d_in[4],
                          (const float*)d_in[6], (const float*)d_in[8],
                          (const float*)d_in[10], (const float*)d_in[12]};
    const float* bs[6] = {(const float*)d_in[3], (const float*)d_in[5],
                          (const float*)d_in[7], (const float*)d_in[9],
                          (const float*)d_in[11], (const float*)d_in[13]};
    const float* Wd = (const float*)d_in[14];
    const float* bd = (const float*)d_in[15];
    float* out = (float*)d_out;

    cudaFuncSetAttribute(k_gemm_mma,
                         cudaFuncAttributeMaxDynamicSharedMemorySize, SMEM_GEMM);

    // CSR build
    k_detect<<<1, 32>>>((const int*)edges);
    k_zero<<<(NN + 255) / 256, 256>>>();
    k_count<<<(NE + 255) / 256, 256>>>(edges);
    k_scan_deg<<<1, 1024>>>();
    k_fill<<<(NE + 255) / 256, 256>>>(edges);

    // x -> bf16 hi/lo (padded K=1536)
    {
        size_t tot = (size_t)MROWS * 1536;
        k_convX<<<(unsigned)((tot + 255) / 256), 256>>>(x);
    }

    const int Kd[5]   = {1475, 512, 512, 256, 256};
    const int Kpad[5] = {1536, 512, 512, 256, 256};
    const int Fd[5]   = {512, 512, 256, 256, 64};

    for (int i = 0; i < 5; i++) {
        int K = Kd[i], Kp = Kpad[i], F = Fd[i];
        int Fpad = (F < 128) ? 128 : F;
        k_convW<<<(Fpad * Kp + 255) / 256, 256>>>(Ws[i], K, F, Kp, Fpad);
        dim3 gg(MROWS / 128, Fpad / 128);
        k_gemm_mma<<<gg, 256, SMEM_GEMM>>>(Kp, F);
        dim3 ga(NN, NB);
        k_agg2<<<ga, 128>>>(bs[i], F, i & 1, i < 4 ? 1 : 0);
    }

    // layer 5: SIMT GEMM + agg (F=3, leaky)
    k_gemm5<<<MROWS / 256, 256>>>(Ws[5]);
    {
        dim3 ga(NN, NB);
        k_agg3<<<ga, 128>>>(bs[5]);
    }

    // dense head
    {
        dim3 gp(DD / 128, 8);
        k_dense_part<<<gp, 128>>>(Wd);
        k_dense_fin<<<(NB * DD + 255) / 256, 256>>>(bd, out);
    }
}